// round 2
// baseline (speedup 1.0000x reference)
#include <cuda_runtime.h>
#include <math.h>

#define NB 256
#define NT 36
#define NS 96
#define ND 1024
#define NH 1024
#define NL 2
#define N3 3072

// ---------------- scratch (device globals; no allocation allowed) ----------------
__device__ float g_h[NL][NB][NH];          // current hidden state per layer
__device__ float g_logits_x[NB][NT][NS];   // precomputed x-part of attn logits (incl. bias)
__device__ float g_combx[NB][NT][ND];      // precomputed x-part of combine (incl. bias); reused as out1 tmp
__device__ float g_lpart[8][NB][NS];       // split-K partials of h-part attn logits
__device__ float g_aw[NB][NS];             // current attn weights
__device__ float g_wenc[NB][NH];           // attention-weighted encoder output
__device__ float g_xc[NB][ND];             // relu(combine)
__device__ float g_gi[2][NB][N3];          // GRU input-gate GEMM partials (split-K=2)
__device__ float g_gh[2][NB][N3];          // GRU hidden-gate GEMM partials
__device__ float g_h1all[NB][NT][NH];      // all layer-1 hidden states (for deferred output GEMMs)

// ---------------- generic SGEMM: C[m,n] = sum_k A[m,k] * W[n,k]  ----------------
// grid.z = split-K chunk index; each chunk writes C + z*czs (partials) over k-range
// [z*kchunk, (z+1)*kchunk). Optional bias[n], add-source, relu.
template<int BM, int BN, int BK>
__global__ __launch_bounds__(256) void sgemm(
    const float* __restrict__ A, int lda,
    const float* __restrict__ W, int ldw,
    float* __restrict__ C, int ldc, long czs,
    const float* __restrict__ addsrc, int add_ld,
    const float* __restrict__ bias,
    int kchunk, int relu)
{
    constexpr int TM = BM / 16;
    constexpr int TN = BN / 16;
    __shared__ float As[BK][BM];
    __shared__ float Ws[BK][BN];

    const int tid = threadIdx.x;
    const int tx = tid & 15;
    const int ty = tid >> 4;
    const int m0 = blockIdx.y * BM;
    const int n0 = blockIdx.x * BN;
    const int kb = blockIdx.z * kchunk;
    C += (long)blockIdx.z * czs;

    float acc[TM][TN];
#pragma unroll
    for (int i = 0; i < TM; i++)
#pragma unroll
        for (int j = 0; j < TN; j++) acc[i][j] = 0.0f;

    for (int k0 = kb; k0 < kb + kchunk; k0 += BK) {
        // load A tile (vectorized float4 along K)
#pragma unroll
        for (int v = tid; v < BM * BK / 4; v += 256) {
            int r = v / (BK / 4);
            int c4 = (v % (BK / 4)) * 4;
            const float4 q = *reinterpret_cast<const float4*>(&A[(long)(m0 + r) * lda + k0 + c4]);
            As[c4 + 0][r] = q.x; As[c4 + 1][r] = q.y;
            As[c4 + 2][r] = q.z; As[c4 + 3][r] = q.w;
        }
        // load W tile
#pragma unroll
        for (int v = tid; v < BN * BK / 4; v += 256) {
            int r = v / (BK / 4);
            int c4 = (v % (BK / 4)) * 4;
            const float4 q = *reinterpret_cast<const float4*>(&W[(long)(n0 + r) * ldw + k0 + c4]);
            Ws[c4 + 0][r] = q.x; Ws[c4 + 1][r] = q.y;
            Ws[c4 + 2][r] = q.z; Ws[c4 + 3][r] = q.w;
        }
        __syncthreads();
#pragma unroll
        for (int kk = 0; kk < BK; kk++) {
            float a[TM], w[TN];
#pragma unroll
            for (int i = 0; i < TM; i++) a[i] = As[kk][ty * TM + i];
#pragma unroll
            for (int j = 0; j < TN; j++) w[j] = Ws[kk][tx * TN + j];
#pragma unroll
            for (int i = 0; i < TM; i++)
#pragma unroll
                for (int j = 0; j < TN; j++) acc[i][j] += a[i] * w[j];
        }
        __syncthreads();
    }

#pragma unroll
    for (int i = 0; i < TM; i++) {
        const int m = m0 + ty * TM + i;
#pragma unroll
        for (int j = 0; j < TN; j++) {
            const int n = n0 + tx * TN + j;
            float v = acc[i][j];
            if (bias)   v += bias[n];
            if (addsrc) v += addsrc[(long)m * add_ld + n];
            if (relu)   v = fmaxf(v, 0.0f);
            C[(long)m * ldc + n] = v;
        }
    }
}

// ---------------- softmax over S=96 (reduces 8 split-K logits partials) ----------------
__global__ void attn_softmax(float* __restrict__ out_attn, int t)
{
    const int b = blockIdx.x * 8 + threadIdx.y;  // 8 warps per block, one row each
    const int lane = threadIdx.x;

    float v[3];
#pragma unroll
    for (int u = 0; u < 3; u++) {
        const int s = u * 32 + lane;
        float x = g_logits_x[b][t][s];
#pragma unroll
        for (int p = 0; p < 8; p++) x += g_lpart[p][b][s];
        v[u] = x;
    }
    float mx = fmaxf(v[0], fmaxf(v[1], v[2]));
#pragma unroll
    for (int o = 16; o > 0; o >>= 1) mx = fmaxf(mx, __shfl_xor_sync(0xffffffffu, mx, o));
    float e[3], sum = 0.0f;
#pragma unroll
    for (int u = 0; u < 3; u++) { e[u] = expf(v[u] - mx); sum += e[u]; }
#pragma unroll
    for (int o = 16; o > 0; o >>= 1) sum += __shfl_xor_sync(0xffffffffu, sum, o);
    const float inv = 1.0f / sum;
#pragma unroll
    for (int u = 0; u < 3; u++) {
        const int s = u * 32 + lane;
        const float w = e[u] * inv;
        g_aw[b][s] = w;
        out_attn[((long)b * NT + t) * NS + s] = w;
    }
}

// ---------------- w_enc[b,:] = aw[b,:] @ enc_output[b,:,:] ----------------
__global__ void wenc_kernel(const float* __restrict__ enc)
{
    const int b = blockIdx.x;
    __shared__ float a[NS];
    const int tid = threadIdx.x;
    if (tid < NS) a[tid] = g_aw[b][tid];
    __syncthreads();

    float4 acc = make_float4(0.f, 0.f, 0.f, 0.f);
    const float4* row = reinterpret_cast<const float4*>(enc + (long)b * NS * NH) + tid;
#pragma unroll 4
    for (int s = 0; s < NS; s++) {
        const float4 q = row[(long)s * (NH / 4)];
        const float w = a[s];
        acc.x += w * q.x; acc.y += w * q.y;
        acc.z += w * q.z; acc.w += w * q.w;
    }
    reinterpret_cast<float4*>(&g_wenc[b][0])[tid] = acc;
}

// ---------------- GRU gates (sums split-K partials; PyTorch r,z,n ordering) ----------------
__global__ void gru_gate(int layer, const float* __restrict__ b_ih,
                         const float* __restrict__ b_hh, int t)
{
    const int idx = blockIdx.x * 256 + threadIdx.x;
    const int b = idx >> 10;
    const int j = idx & 1023;
    const float* bi = b_ih + layer * N3;
    const float* bh = b_hh + layer * N3;

    const float ir = g_gi[0][b][j]          + g_gi[1][b][j]          + bi[j];
    const float hr = g_gh[0][b][j]          + g_gh[1][b][j]          + bh[j];
    const float iz = g_gi[0][b][j + NH]     + g_gi[1][b][j + NH]     + bi[j + NH];
    const float hz = g_gh[0][b][j + NH]     + g_gh[1][b][j + NH]     + bh[j + NH];
    const float in_ = g_gi[0][b][j + 2*NH]  + g_gi[1][b][j + 2*NH]   + bi[j + 2*NH];
    const float hn = g_gh[0][b][j + 2*NH]   + g_gh[1][b][j + 2*NH]   + bh[j + 2*NH];

    const float r = 1.0f / (1.0f + expf(-(ir + hr)));
    const float z = 1.0f / (1.0f + expf(-(iz + hz)));
    const float n = tanhf(in_ + r * hn);
    const float h = (1.0f - z) * n + z * g_h[layer][b][j];

    g_h[layer][b][j] = h;
    if (t >= 0) g_h1all[b][t][j] = h;   // layer 1 only: record for deferred output GEMM
}

__global__ void copy_kernel(float* __restrict__ dst, const float* __restrict__ src)
{
    const long i = (long)blockIdx.x * 256 + threadIdx.x;
    dst[i] = src[i];
}

// ---------------- launch ----------------
extern "C" void kernel_launch(void* const* d_in, const int* in_sizes, int n_in,
                              void* d_out, int out_size)
{
    const float* target = (const float*)d_in[0];   // (B, T, D)
    const float* hidden = (const float*)d_in[1];   // (L, B, H)
    const float* enc    = (const float*)d_in[2];   // (B, S, H)
    const float* aW     = (const float*)d_in[3];   // (S, D+H)
    const float* ab     = (const float*)d_in[4];   // (S,)
    const float* cW     = (const float*)d_in[5];   // (D, D+H)
    const float* cb     = (const float*)d_in[6];   // (D,)
    const float* Wih    = (const float*)d_in[7];   // (L, 3H, D)
    const float* Whh    = (const float*)d_in[8];   // (L, 3H, H)
    const float* bih    = (const float*)d_in[9];   // (L, 3H)
    const float* bhh    = (const float*)d_in[10];  // (L, 3H)
    const float* o1W    = (const float*)d_in[11];  // (D, H)
    const float* o1b    = (const float*)d_in[12];
    const float* o2W    = (const float*)d_in[13];  // (D, D)
    const float* o2b    = (const float*)d_in[14];

    // output layout: output (B,T,D) | hidden_f (L,B,H) | attn_weights (B,T,S)
    float* out_y    = (float*)d_out;
    float* out_h    = out_y + (long)NB * NT * ND;
    float* out_attn = out_h + (long)NL * NB * NH;

    float *ph, *plx, *pcx, *plp, *pwe, *pxc, *pgi, *pgh, *ph1a;
    cudaGetSymbolAddress((void**)&ph,   g_h);
    cudaGetSymbolAddress((void**)&plx,  g_logits_x);
    cudaGetSymbolAddress((void**)&pcx,  g_combx);
    cudaGetSymbolAddress((void**)&plp,  g_lpart);
    cudaGetSymbolAddress((void**)&pwe,  g_wenc);
    cudaGetSymbolAddress((void**)&pxc,  g_xc);
    cudaGetSymbolAddress((void**)&pgi,  g_gi);
    cudaGetSymbolAddress((void**)&pgh,  g_gh);
    cudaGetSymbolAddress((void**)&ph1a, g_h1all);

    float* ph0 = ph;                 // g_h[0]
    float* ph1 = ph + (long)NB * NH; // g_h[1]

    // init hidden state
    copy_kernel<<<NL * NB * NH / 256, 256>>>(ph, hidden);

    // ---- precompute (x-parts, off critical path) ----
    // logits_x = target @ aW[:, :D].T + ab   (M=9216, N=96, K=1024)
    sgemm<64, 32, 16><<<dim3(NS / 32, (NB * NT) / 64, 1), 256>>>(
        target, ND, aW, ND + NH, plx, NS, 0, nullptr, 0, ab, ND, 0);
    // combx = target @ cW[:, :D].T + cb      (M=9216, N=1024, K=1024)
    sgemm<64, 64, 16><<<dim3(ND / 64, (NB * NT) / 64, 1), 256>>>(
        target, ND, cW, ND + NH, pcx, ND, 0, nullptr, 0, cb, ND, 0);

    // ---- recurrent loop ----
    for (int t = 0; t < NT; t++) {
        // h-part of attn logits: h1 @ aW[:, D:].T  (split-K=8 partials)
        sgemm<32, 32, 16><<<dim3(NS / 32, NB / 32, 8), 256>>>(
            ph1, NH, aW + ND, ND + NH, plp, NS, (long)NB * NS,
            nullptr, 0, nullptr, NH / 8, 0);
        attn_softmax<<<NB / 8, dim3(32, 8)>>>(out_attn, t);
        wenc_kernel<<<NB, 256>>>(enc);
        // xc = relu(combx[:,t,:] + wenc @ cW[:, D:].T)
        sgemm<32, 64, 16><<<dim3(ND / 64, NB / 32, 1), 256>>>(
            pwe, NH, cW + ND, ND + NH, pxc, ND, 0,
            pcx + (long)t * ND, NT * ND, nullptr, NH, 1);

        // GRU layer 0 (split-K=2)
        sgemm<64, 64, 16><<<dim3(N3 / 64, NB / 64, 2), 256>>>(
            pxc, ND, Wih, ND, pgi, N3, (long)NB * N3, nullptr, 0, nullptr, ND / 2, 0);
        sgemm<64, 64, 16><<<dim3(N3 / 64, NB / 64, 2), 256>>>(
            ph0, NH, Whh, NH, pgh, N3, (long)NB * N3, nullptr, 0, nullptr, NH / 2, 0);
        gru_gate<<<NB * NH / 256, 256>>>(0, bih, bhh, -1);

        // GRU layer 1
        sgemm<64, 64, 16><<<dim3(N3 / 64, NB / 64, 2), 256>>>(
            ph0, NH, Wih + (long)N3 * ND, ND, pgi, N3, (long)NB * N3, nullptr, 0, nullptr, ND / 2, 0);
        sgemm<64, 64, 16><<<dim3(N3 / 64, NB / 64, 2), 256>>>(
            ph1, NH, Whh + (long)N3 * NH, NH, pgh, N3, (long)NB * N3, nullptr, 0, nullptr, NH / 2, 0);
        gru_gate<<<NB * NH / 256, 256>>>(1, bih, bhh, t);
    }

    // ---- deferred output head (reuses g_combx as tmp) ----
    sgemm<64, 64, 16><<<dim3(ND / 64, (NB * NT) / 64, 1), 256>>>(
        ph1a, NH, o1W, NH, pcx, ND, 0, nullptr, 0, o1b, NH, 0);
    sgemm<64, 64, 16><<<dim3(ND / 64, (NB * NT) / 64, 1), 256>>>(
        pcx, ND, o2W, ND, out_y, ND, 0, nullptr, 0, o2b, ND, 0);

    // final hidden state
    copy_kernel<<<NL * NB * NH / 256, 256>>>(out_h, ph);
}

// round 3
// speedup vs baseline: 2.3943x; 2.3943x over previous
#include <cuda_runtime.h>
#include <cuda_bf16.h>
#include <math.h>
#include <stdint.h>

#define NB 256
#define NT 36
#define NS 96
#define ND 1024
#define NH 1024
#define N3 3072

// ===================== device scratch (no allocations allowed) =====================
__device__ __align__(16) __nv_bfloat16 g_th[9216*1024], g_tl[9216*1024];     // target split
__device__ __align__(16) __nv_bfloat16 g_aWh[96*2048],  g_aWl[96*2048];      // attn_w split
__device__ __align__(16) __nv_bfloat16 g_cWh[1024*2048], g_cWl[1024*2048];   // combine split
__device__ __align__(16) __nv_bfloat16 g_Wgh[2*2*3072*1024], g_Wgl[2*2*3072*1024]; // [l][ih/hh][3072][1024]
__device__ __align__(16) __nv_bfloat16 g_o1h[1024*1024], g_o1l[1024*1024];
__device__ __align__(16) __nv_bfloat16 g_o2h[1024*1024], g_o2l[1024*1024];
__device__ __align__(16) __nv_bfloat16 g_tmph[9216*1024], g_tmpl[9216*1024]; // out1 result split
__device__ __align__(16) __nv_bfloat16 g_h1h[9216*1024], g_h1l[9216*1024];   // all h1 states split
__device__ float g_combx[9216*1024];       // x-part of combine (fp32)
__device__ float g_lx[9216*96];            // x-part of attn logits
__device__ float g_lpart[4*256*96];        // split-K partials of h-part logits
__device__ float g_aw[256*96];             // softmax weights
__device__ __align__(16) __nv_bfloat16 g_weh[256*1024], g_wel[256*1024];     // wenc split
__device__ __align__(16) __nv_bfloat16 g_a0h[256*2048], g_a0l[256*2048];     // [xc | h0] split
__device__ __align__(16) __nv_bfloat16 g_a1h[256*2048], g_a1l[256*2048];     // [h0new | h1] split
__device__ float g_g[2*256*3072];          // gi / gh fp32
__device__ float g_hf[2*256*1024];         // fp32 hidden

// ===================== mma helpers =====================
__device__ __forceinline__ void ldsm4(uint32_t &r0, uint32_t &r1, uint32_t &r2, uint32_t &r3,
                                      const __nv_bfloat16* p) {
    uint32_t a = (uint32_t)__cvta_generic_to_shared(p);
    asm volatile("ldmatrix.sync.aligned.m8n8.x4.shared.b16 {%0,%1,%2,%3},[%4];"
                 : "=r"(r0), "=r"(r1), "=r"(r2), "=r"(r3) : "r"(a));
}
__device__ __forceinline__ void mma16816(float* c, const uint32_t* a, const uint32_t* b) {
    asm volatile("mma.sync.aligned.m16n8k16.row.col.f32.bf16.bf16.f32 "
                 "{%0,%1,%2,%3},{%4,%5,%6,%7},{%8,%9},{%0,%1,%2,%3};"
                 : "+f"(c[0]), "+f"(c[1]), "+f"(c[2]), "+f"(c[3])
                 : "r"(a[0]), "r"(a[1]), "r"(a[2]), "r"(a[3]), "r"(b[0]), "r"(b[1]));
}

// ===================== split-bf16 GEMM: C[m,n] = sum_k A[m,k]*W[n,k] =====================
// 3 passes: A_hi*W_hi + A_hi*W_lo + A_lo*W_hi  (fp32 accumulate)
struct GP {
    const __nv_bfloat16 *Ah, *Al; long lda, saz;   // A z-stride (elems)
    const __nv_bfloat16 *Wh, *Wl; long ldw, swz;   // W z-stride
    float* Cf; long scz;                           // fp32 out (+ z stride)
    __nv_bfloat16 *Chi, *Clo; long ldc;            // split-bf16 out
    const float* bias; const float* add; long add_ld;
    int relu; int K; long kz;                      // split-K: kstart = z*kz
};

template<int BM, int BN, int WM, int WN>
__global__ void __launch_bounds__((BM/WM)*(BN/WN)*32)
gemm_bf16(GP p)
{
    constexpr int BK = 32, PAD = 8;
    constexpr int WPM = BM/WM, WPN = BN/WN, T = WPM*WPN*32;
    constexpr int MI = WM/16, NI = WN/8;
    __shared__ __align__(16) __nv_bfloat16 As[BM][BK+PAD];
    __shared__ __align__(16) __nv_bfloat16 Bs[BN][BK+PAD];

    const int tid = threadIdx.x, lane = tid & 31, wid = tid >> 5;
    const int wm0 = (wid % WPM) * WM, wn0 = (wid / WPM) * WN;
    const int m0 = blockIdx.y * BM, n0 = blockIdx.x * BN, z = blockIdx.z;

    const __nv_bfloat16 *Ah = p.Ah + (long)z * p.saz, *Al = p.Al + (long)z * p.saz;
    const __nv_bfloat16 *Wh = p.Wh + (long)z * p.swz, *Wl = p.Wl + (long)z * p.swz;
    const long k0base = (long)z * p.kz;

    float c[MI][NI][4];
#pragma unroll
    for (int mi = 0; mi < MI; mi++)
#pragma unroll
        for (int ni = 0; ni < NI; ni++)
#pragma unroll
            for (int q = 0; q < 4; q++) c[mi][ni][q] = 0.0f;

    const int aRow = lane & 15, aCol = (lane >> 4) * 8;
    const int bRow = ((lane >> 4) & 1) * 8 + (lane & 7), bKoff = ((lane >> 3) & 1) * 8;

    for (int pass = 0; pass < 3; pass++) {
        const __nv_bfloat16* Ap = (pass < 2) ? Ah : Al;
        const __nv_bfloat16* Wp = (pass == 1) ? Wl : Wh;
        for (long k0 = k0base; k0 < k0base + p.K; k0 += BK) {
#pragma unroll
            for (int i = 0; i < BM*4/T; i++) {
                int idx = tid + i*T; int r = idx >> 2, cc = (idx & 3) * 8;
                *(uint4*)&As[r][cc] = *(const uint4*)(Ap + (long)(m0 + r) * p.lda + k0 + cc);
            }
#pragma unroll
            for (int i = 0; i < BN*4/T; i++) {
                int idx = tid + i*T; int r = idx >> 2, cc = (idx & 3) * 8;
                *(uint4*)&Bs[r][cc] = *(const uint4*)(Wp + (long)(n0 + r) * p.ldw + k0 + cc);
            }
            __syncthreads();
#pragma unroll
            for (int kk = 0; kk < 2; kk++) {
                uint32_t a[MI][4];
#pragma unroll
                for (int mi = 0; mi < MI; mi++)
                    ldsm4(a[mi][0], a[mi][1], a[mi][2], a[mi][3],
                          &As[wm0 + mi*16 + aRow][kk*16 + aCol]);
                uint32_t b[NI][2];
#pragma unroll
                for (int j2 = 0; j2 < NI/2; j2++) {
                    uint32_t r0, r1, r2, r3;
                    ldsm4(r0, r1, r2, r3, &Bs[wn0 + j2*16 + bRow][kk*16 + bKoff]);
                    b[2*j2][0] = r0; b[2*j2][1] = r1; b[2*j2+1][0] = r2; b[2*j2+1][1] = r3;
                }
#pragma unroll
                for (int mi = 0; mi < MI; mi++)
#pragma unroll
                    for (int ni = 0; ni < NI; ni++) mma16816(c[mi][ni], a[mi], b[ni]);
            }
            __syncthreads();
        }
    }

    float* Cf = p.Cf ? p.Cf + (long)z * p.scz : nullptr;
#pragma unroll
    for (int mi = 0; mi < MI; mi++) {
#pragma unroll
        for (int ni = 0; ni < NI; ni++) {
            const int col = n0 + wn0 + ni*8 + (lane & 3)*2;
            float b0 = 0.f, b1 = 0.f;
            if (p.bias) { b0 = p.bias[col]; b1 = p.bias[col+1]; }
#pragma unroll
            for (int h = 0; h < 2; h++) {
                const int r = m0 + wm0 + mi*16 + (lane >> 2) + h*8;
                float v0 = c[mi][ni][h*2] + b0, v1 = c[mi][ni][h*2+1] + b1;
                if (p.add) { const float* ap = p.add + (long)r * p.add_ld + col; v0 += ap[0]; v1 += ap[1]; }
                if (p.relu) { v0 = fmaxf(v0, 0.f); v1 = fmaxf(v1, 0.f); }
                if (Cf) *(float2*)&Cf[(long)r * p.ldc + col] = make_float2(v0, v1);
                if (p.Chi) {
                    __nv_bfloat16 h0 = __float2bfloat16(v0), h1 = __float2bfloat16(v1);
                    __nv_bfloat162 hh; hh.x = h0; hh.y = h1;
                    *(__nv_bfloat162*)&p.Chi[(long)r * p.ldc + col] = hh;
                    __nv_bfloat162 ll;
                    ll.x = __float2bfloat16(v0 - __bfloat162float(h0));
                    ll.y = __float2bfloat16(v1 - __bfloat162float(h1));
                    *(__nv_bfloat162*)&p.Clo[(long)r * p.ldc + col] = ll;
                }
            }
        }
    }
}

// ===================== small kernels =====================
__global__ void k_split(__nv_bfloat16* hh, __nv_bfloat16* ll, const float* s, long n)
{
    long i = (long)blockIdx.x * 256 + threadIdx.x;
    if (i >= n) return;
    float v = s[i];
    __nv_bfloat16 h = __float2bfloat16(v);
    hh[i] = h; ll[i] = __float2bfloat16(v - __bfloat162float(h));
}

__global__ void k_inith(const float* hidden)
{
    long idx = (long)blockIdx.x * 256 + threadIdx.x;  // 2*256*1024
    float v = hidden[idx];
    g_hf[idx] = v;
    int l = (int)(idx >> 18); long rem = idx & 262143;
    int b = (int)(rem >> 10), j = (int)(rem & 1023);
    __nv_bfloat16 h = __float2bfloat16(v);
    __nv_bfloat16 lo = __float2bfloat16(v - __bfloat162float(h));
    __nv_bfloat16* dh = l ? g_a1h : g_a0h;
    __nv_bfloat16* dl = l ? g_a1l : g_a0l;
    dh[b*2048 + 1024 + j] = h; dl[b*2048 + 1024 + j] = lo;
}

__global__ void k_softmax(float* __restrict__ out_attn, int t)
{
    const int b = blockIdx.x * 8 + threadIdx.y;
    const int lane = threadIdx.x;
    float v[3];
#pragma unroll
    for (int u = 0; u < 3; u++) {
        const int s = u*32 + lane;
        float x = g_lx[((long)b*NT + t)*NS + s];
#pragma unroll
        for (int p = 0; p < 4; p++) x += g_lpart[p*24576 + b*NS + s];
        v[u] = x;
    }
    float mx = fmaxf(v[0], fmaxf(v[1], v[2]));
#pragma unroll
    for (int o = 16; o > 0; o >>= 1) mx = fmaxf(mx, __shfl_xor_sync(0xffffffffu, mx, o));
    float e[3], sum = 0.f;
#pragma unroll
    for (int u = 0; u < 3; u++) { e[u] = expf(v[u] - mx); sum += e[u]; }
#pragma unroll
    for (int o = 16; o > 0; o >>= 1) sum += __shfl_xor_sync(0xffffffffu, sum, o);
    const float inv = 1.0f / sum;
#pragma unroll
    for (int u = 0; u < 3; u++) {
        const int s = u*32 + lane;
        const float w = e[u] * inv;
        g_aw[b*NS + s] = w;
        out_attn[((long)b*NT + t)*NS + s] = w;
    }
}

__global__ void k_wenc(const float* __restrict__ enc)
{
    const int b = blockIdx.x, tid = threadIdx.x;
    __shared__ float a[NS];
    if (tid < NS) a[tid] = g_aw[b*NS + tid];
    __syncthreads();
    float4 acc = make_float4(0.f, 0.f, 0.f, 0.f);
    const float4* row = reinterpret_cast<const float4*>(enc + (long)b*NS*NH) + tid;
#pragma unroll 4
    for (int s = 0; s < NS; s++) {
        const float4 q = row[(long)s * (NH/4)];
        const float w = a[s];
        acc.x += w*q.x; acc.y += w*q.y; acc.z += w*q.z; acc.w += w*q.w;
    }
    const int base = b*1024 + tid*4;
    float vv[4] = {acc.x, acc.y, acc.z, acc.w};
#pragma unroll
    for (int i = 0; i < 4; i++) {
        __nv_bfloat16 h = __float2bfloat16(vv[i]);
        g_weh[base + i] = h;
        g_wel[base + i] = __float2bfloat16(vv[i] - __bfloat162float(h));
    }
}

__global__ void k_gate(const float* __restrict__ bi, const float* __restrict__ bh,
                       float* __restrict__ hf,
                       __nv_bfloat16* d1h, __nv_bfloat16* d1l,
                       __nv_bfloat16* d2h, __nv_bfloat16* d2l,
                       __nv_bfloat16* d3h, __nv_bfloat16* d3l, long d3off)
{
    const int idx = blockIdx.x * 256 + threadIdx.x;
    const int b = idx >> 10, j = idx & 1023;
    const float* gi = g_g + (long)b * N3;
    const float* gh = g_g + 786432 + (long)b * N3;
    const float ir = gi[j] + bi[j],           hr = gh[j] + bh[j];
    const float iz = gi[j+1024] + bi[j+1024], hz = gh[j+1024] + bh[j+1024];
    const float in_ = gi[j+2048] + bi[j+2048], hn = gh[j+2048] + bh[j+2048];
    const float r = 1.0f / (1.0f + expf(-(ir + hr)));
    const float z = 1.0f / (1.0f + expf(-(iz + hz)));
    const float n = tanhf(in_ + r * hn);
    const float h = (1.0f - z) * n + z * hf[idx];
    hf[idx] = h;
    __nv_bfloat16 hh = __float2bfloat16(h);
    __nv_bfloat16 hl = __float2bfloat16(h - __bfloat162float(hh));
    const long o = (long)b*2048 + j;
    d1h[o] = hh; d1l[o] = hl;
    if (d2h) { d2h[o] = hh; d2l[o] = hl; }
    if (d3h) { const long o3 = (long)b*36864 + d3off + j; d3h[o3] = hh; d3l[o3] = hl; }
}

__global__ void k_copy(float* __restrict__ dst, const float* __restrict__ src)
{
    const long i = (long)blockIdx.x * 256 + threadIdx.x;
    dst[i] = src[i];
}

// ===================== launch =====================
extern "C" void kernel_launch(void* const* d_in, const int* in_sizes, int n_in,
                              void* d_out, int out_size)
{
    const float* target = (const float*)d_in[0];
    const float* hidden = (const float*)d_in[1];
    const float* enc    = (const float*)d_in[2];
    const float* aW     = (const float*)d_in[3];
    const float* ab     = (const float*)d_in[4];
    const float* cW     = (const float*)d_in[5];
    const float* cb     = (const float*)d_in[6];
    const float* Wih    = (const float*)d_in[7];
    const float* Whh    = (const float*)d_in[8];
    const float* bih    = (const float*)d_in[9];
    const float* bhh    = (const float*)d_in[10];
    const float* o1W    = (const float*)d_in[11];
    const float* o1b    = (const float*)d_in[12];
    const float* o2W    = (const float*)d_in[13];
    const float* o2b    = (const float*)d_in[14];

    float* out_y    = (float*)d_out;
    float* out_h    = out_y + (long)NB*NT*ND;
    float* out_attn = out_h + (long)2*NB*NH;

    __nv_bfloat16 *th, *tl, *aWh, *aWl, *cWh, *cWl, *Wgh, *Wgl, *o1h, *o1l, *o2h, *o2l;
    __nv_bfloat16 *tmph, *tmpl, *h1h, *h1l, *weh, *wel, *a0h, *a0l, *a1h, *a1l;
    float *combx, *lx, *lpart, *gg, *hf;
    cudaGetSymbolAddress((void**)&th, g_th);     cudaGetSymbolAddress((void**)&tl, g_tl);
    cudaGetSymbolAddress((void**)&aWh, g_aWh);   cudaGetSymbolAddress((void**)&aWl, g_aWl);
    cudaGetSymbolAddress((void**)&cWh, g_cWh);   cudaGetSymbolAddress((void**)&cWl, g_cWl);
    cudaGetSymbolAddress((void**)&Wgh, g_Wgh);   cudaGetSymbolAddress((void**)&Wgl, g_Wgl);
    cudaGetSymbolAddress((void**)&o1h, g_o1h);   cudaGetSymbolAddress((void**)&o1l, g_o1l);
    cudaGetSymbolAddress((void**)&o2h, g_o2h);   cudaGetSymbolAddress((void**)&o2l, g_o2l);
    cudaGetSymbolAddress((void**)&tmph, g_tmph); cudaGetSymbolAddress((void**)&tmpl, g_tmpl);
    cudaGetSymbolAddress((void**)&h1h, g_h1h);   cudaGetSymbolAddress((void**)&h1l, g_h1l);
    cudaGetSymbolAddress((void**)&weh, g_weh);   cudaGetSymbolAddress((void**)&wel, g_wel);
    cudaGetSymbolAddress((void**)&a0h, g_a0h);   cudaGetSymbolAddress((void**)&a0l, g_a0l);
    cudaGetSymbolAddress((void**)&a1h, g_a1h);   cudaGetSymbolAddress((void**)&a1l, g_a1l);
    cudaGetSymbolAddress((void**)&combx, g_combx);
    cudaGetSymbolAddress((void**)&lx, g_lx);
    cudaGetSymbolAddress((void**)&lpart, g_lpart);
    cudaGetSymbolAddress((void**)&gg, g_g);
    cudaGetSymbolAddress((void**)&hf, g_hf);

    // ---- one-time conversions (inside graph; cheap) ----
    auto grid1 = [](long n) { return (unsigned)((n + 255) / 256); };
    k_split<<<grid1(9216L*1024), 256>>>(th, tl, target, 9216L*1024);
    k_split<<<grid1(96L*2048), 256>>>(aWh, aWl, aW, 96L*2048);
    k_split<<<grid1(1024L*2048), 256>>>(cWh, cWl, cW, 1024L*2048);
    for (int l = 0; l < 2; l++) {
        k_split<<<grid1(3145728), 256>>>(Wgh + (long)(l*2+0)*3145728, Wgl + (long)(l*2+0)*3145728,
                                         Wih + (long)l*3145728, 3145728);
        k_split<<<grid1(3145728), 256>>>(Wgh + (long)(l*2+1)*3145728, Wgl + (long)(l*2+1)*3145728,
                                         Whh + (long)l*3145728, 3145728);
    }
    k_split<<<grid1(1048576), 256>>>(o1h, o1l, o1W, 1048576);
    k_split<<<grid1(1048576), 256>>>(o2h, o2l, o2W, 1048576);
    k_inith<<<2048, 256>>>(hidden);

    GP p = {};

    // ---- pre: x-parts ----
    // logits_x = target @ aW[:, :D].T + ab
    p = {}; p.Ah = th; p.Al = tl; p.lda = 1024; p.Wh = aWh; p.Wl = aWl; p.ldw = 2048;
    p.Cf = lx; p.ldc = 96; p.bias = ab; p.K = 1024;
    gemm_bf16<64,32,32,16><<<dim3(3,144,1), 128>>>(p);
    // combx = target @ cW[:, :D].T + cb
    p = {}; p.Ah = th; p.Al = tl; p.lda = 1024; p.Wh = cWh; p.Wl = cWl; p.ldw = 2048;
    p.Cf = combx; p.ldc = 1024; p.bias = cb; p.K = 1024;
    gemm_bf16<128,128,64,32><<<dim3(8,72,1), 256>>>(p);

    // ---- recurrent loop ----
    for (int t = 0; t < NT; t++) {
        // h-part of attn logits: h1 @ aW[:, D:].T  (split-K=4 partials)
        p = {}; p.Ah = a1h + 1024; p.Al = a1l + 1024; p.lda = 2048;
        p.Wh = aWh + 1024; p.Wl = aWl + 1024; p.ldw = 2048;
        p.Cf = lpart; p.scz = 24576; p.ldc = 96; p.K = 256; p.kz = 256;
        gemm_bf16<64,32,32,16><<<dim3(3,4,4), 128>>>(p);

        k_softmax<<<32, dim3(32,8)>>>(out_attn, t);
        k_wenc<<<256, 256>>>(enc);

        // xc = relu(combx[:,t,:] + wenc @ cW[:, D:].T)  -> split bf16 into a0[:, 0:1024]
        p = {}; p.Ah = weh; p.Al = wel; p.lda = 1024;
        p.Wh = cWh + 1024; p.Wl = cWl + 1024; p.ldw = 2048;
        p.Chi = a0h; p.Clo = a0l; p.ldc = 2048;
        p.add = combx + (long)t*1024; p.add_ld = 36864; p.relu = 1; p.K = 1024;
        gemm_bf16<64,32,32,16><<<dim3(32,4,1), 128>>>(p);

        // GRU layer 0: z=0 -> gi = xc@Wih0.T, z=1 -> gh = h0@Whh0.T
        p = {}; p.Ah = a0h; p.Al = a0l; p.lda = 2048; p.saz = 1024;
        p.Wh = Wgh; p.Wl = Wgl; p.ldw = 1024; p.swz = 3145728;
        p.Cf = gg; p.scz = 786432; p.ldc = 3072; p.K = 1024;
        gemm_bf16<64,64,32,32><<<dim3(48,4,2), 128>>>(p);
        k_gate<<<1024, 256>>>(bih, bhh, hf, a1h, a1l, a0h + 1024, a0l + 1024,
                              nullptr, nullptr, 0);

        // GRU layer 1
        p = {}; p.Ah = a1h; p.Al = a1l; p.lda = 2048; p.saz = 1024;
        p.Wh = Wgh + 2L*3145728; p.Wl = Wgl + 2L*3145728; p.ldw = 1024; p.swz = 3145728;
        p.Cf = gg; p.scz = 786432; p.ldc = 3072; p.K = 1024;
        gemm_bf16<64,64,32,32><<<dim3(48,4,2), 128>>>(p);
        k_gate<<<1024, 256>>>(bih + 3072, bhh + 3072, hf + 262144, a1h + 1024, a1l + 1024,
                              nullptr, nullptr, h1h, h1l, (long)t*1024);
    }

    // ---- deferred output head ----
    p = {}; p.Ah = h1h; p.Al = h1l; p.lda = 1024; p.Wh = o1h; p.Wl = o1l; p.ldw = 1024;
    p.Chi = tmph; p.Clo = tmpl; p.ldc = 1024; p.bias = o1b; p.K = 1024;
    gemm_bf16<128,128,64,32><<<dim3(8,72,1), 256>>>(p);
    p = {}; p.Ah = tmph; p.Al = tmpl; p.lda = 1024; p.Wh = o2h; p.Wl = o2l; p.ldw = 1024;
    p.Cf = out_y; p.ldc = 1024; p.bias = o2b; p.K = 1024;
    gemm_bf16<128,128,64,32><<<dim3(8,72,1), 256>>>(p);

    k_copy<<<2048, 256>>>(out_h, hf);
}

// round 4
// speedup vs baseline: 4.0660x; 1.6982x over previous
#include <cuda_runtime.h>
#include <cuda_bf16.h>
#include <math.h>
#include <stdint.h>

#define NB 256
#define NT 36
#define NS 96
#define ND 1024
#define NH 1024
#define N3 3072

// ===================== device scratch =====================
__device__ __align__(16) __nv_bfloat16 g_th[9216*1024], g_tl[9216*1024];
__device__ __align__(16) __nv_bfloat16 g_aWh[96*2048],  g_aWl[96*2048];
__device__ __align__(16) __nv_bfloat16 g_cWh[1024*2048], g_cWl[1024*2048];
__device__ __align__(16) __nv_bfloat16 g_Wgh[2*2*3072*1024], g_Wgl[2*2*3072*1024];
__device__ __align__(16) __nv_bfloat16 g_o1h[1024*1024], g_o1l[1024*1024];
__device__ __align__(16) __nv_bfloat16 g_o2h[1024*1024], g_o2l[1024*1024];
__device__ __align__(16) __nv_bfloat16 g_tmph[9216*1024], g_tmpl[9216*1024];
__device__ __align__(16) __nv_bfloat16 g_h1h[9216*1024], g_h1l[9216*1024];
__device__ float g_combx[9216*1024];
__device__ float g_lx[9216*96];
__device__ float g_lpart[4*256*96];
__device__ __align__(16) __nv_bfloat16 g_weh[256*1024], g_wel[256*1024];
__device__ __align__(16) __nv_bfloat16 g_a0h[256*2048], g_a0l[256*2048];
__device__ __align__(16) __nv_bfloat16 g_a1h[256*2048], g_a1l[256*2048];
__device__ float g_g[2*256*3072];
__device__ float g_hf[2*256*1024];

// ===================== mma / async helpers =====================
__device__ __forceinline__ void ldsm4(uint32_t &r0, uint32_t &r1, uint32_t &r2, uint32_t &r3,
                                      const __nv_bfloat16* p) {
    uint32_t a = (uint32_t)__cvta_generic_to_shared(p);
    asm volatile("ldmatrix.sync.aligned.m8n8.x4.shared.b16 {%0,%1,%2,%3},[%4];"
                 : "=r"(r0), "=r"(r1), "=r"(r2), "=r"(r3) : "r"(a));
}
__device__ __forceinline__ void mma16816(float* c, const uint32_t* a, const uint32_t* b) {
    asm volatile("mma.sync.aligned.m16n8k16.row.col.f32.bf16.bf16.f32 "
                 "{%0,%1,%2,%3},{%4,%5,%6,%7},{%8,%9},{%0,%1,%2,%3};"
                 : "+f"(c[0]), "+f"(c[1]), "+f"(c[2]), "+f"(c[3])
                 : "r"(a[0]), "r"(a[1]), "r"(a[2]), "r"(a[3]), "r"(b[0]), "r"(b[1]));
}
__device__ __forceinline__ void cpa16(uint32_t dst, const __nv_bfloat16* src) {
    asm volatile("cp.async.cg.shared.global [%0], [%1], 16;"
                 :: "r"(dst), "l"(__cvta_generic_to_global(src)));
}

// ===================== pipelined split-bf16 GEMM =====================
// C[m,n] = sum_k A[m,k]*W[n,k], 3 interleaved passes (AhWh+AhWl+AlWh), fp32 acc
struct GP {
    const __nv_bfloat16 *Ah, *Al; long lda, saz;
    const __nv_bfloat16 *Wh, *Wl; long ldw, swz;
    float* Cf; long scz;
    __nv_bfloat16 *Chi, *Clo; long ldc;
    const float* bias; const float* add; long add_ld;
    int relu; int K; long kz;
};

template<int BM, int BN, int WM, int WN>
__global__ void __launch_bounds__((BM/WM)*(BN/WN)*32)
gemm_bf16(GP p)
{
    constexpr int BK = 32, LDSH = BK + 8;              // halves per smem row
    constexpr int WPM = BM/WM, WPN = BN/WN, T = WPM*WPN*32;
    constexpr int MI = WM/16, NI = WN/8;
    // [stage][hi/lo][A rows BM | B rows BN][LDSH]
    __shared__ __align__(16) __nv_bfloat16 sm[2][2][(BM+BN)*LDSH];

    const int tid = threadIdx.x, lane = tid & 31, wid = tid >> 5;
    const int wm0 = (wid % WPM) * WM, wn0 = (wid / WPM) * WN;
    const int m0 = blockIdx.y * BM, n0 = blockIdx.x * BN, z = blockIdx.z;

    const __nv_bfloat16 *Ah = p.Ah + (long)z * p.saz, *Al = p.Al + (long)z * p.saz;
    const __nv_bfloat16 *Wh = p.Wh + (long)z * p.swz, *Wl = p.Wl + (long)z * p.swz;
    const long kstart = (long)z * p.kz;
    const int niter = p.K / BK;

    const uint32_t smbase = (uint32_t)__cvta_generic_to_shared(&sm[0][0][0]);
    constexpr uint32_t LST = (BM+BN)*LDSH*2;   // hi->lo byte stride
    constexpr uint32_t SST = 2*LST;            // stage byte stride
    constexpr uint32_t BOFF = BM*LDSH*2;       // A->B byte offset

    float c[MI][NI][4];
#pragma unroll
    for (int mi = 0; mi < MI; mi++)
#pragma unroll
        for (int ni = 0; ni < NI; ni++)
#pragma unroll
            for (int q = 0; q < 4; q++) c[mi][ni][q] = 0.0f;

    auto issue = [&](int s, long gk) {
        const uint32_t sb = smbase + s*SST;
#pragma unroll
        for (int i = 0; i < BM*4/T; i++) {
            int idx = tid + i*T; int r = idx >> 2; int c16 = idx & 3;
            long go = (long)(m0 + r) * p.lda + gk + c16*8;
            uint32_t d = sb + r*(LDSH*2) + c16*16;
            cpa16(d, Ah + go);
            cpa16(d + LST, Al + go);
        }
#pragma unroll
        for (int i = 0; i < BN*4/T; i++) {
            int idx = tid + i*T; int r = idx >> 2; int c16 = idx & 3;
            long go = (long)(n0 + r) * p.ldw + gk + c16*8;
            uint32_t d = sb + BOFF + r*(LDSH*2) + c16*16;
            cpa16(d, Wh + go);
            cpa16(d + LST, Wl + go);
        }
        asm volatile("cp.async.commit_group;");
    };

    const int aRow = lane & 15, aCol = (lane >> 4) * 8;
    const int bRow = ((lane >> 4) & 1) * 8 + (lane & 7), bKoff = ((lane >> 3) & 1) * 8;

    issue(0, kstart);
    for (int k = 0; k < niter; k++) {
        const int s = k & 1;
        if (k + 1 < niter) {
            issue(s ^ 1, kstart + (long)(k+1)*BK);
            asm volatile("cp.async.wait_group 1;");
        } else {
            asm volatile("cp.async.wait_group 0;");
        }
        __syncthreads();
#pragma unroll
        for (int kk = 0; kk < 2; kk++) {
            uint32_t ah[MI][4], al[MI][4];
#pragma unroll
            for (int mi = 0; mi < MI; mi++) {
                const int ro = (wm0 + mi*16 + aRow)*LDSH + kk*16 + aCol;
                ldsm4(ah[mi][0], ah[mi][1], ah[mi][2], ah[mi][3], &sm[s][0][ro]);
                ldsm4(al[mi][0], al[mi][1], al[mi][2], al[mi][3], &sm[s][1][ro]);
            }
            uint32_t wh[NI][2], wl[NI][2];
#pragma unroll
            for (int j2 = 0; j2 < NI/2; j2++) {
                const int ro = BM*LDSH + (wn0 + j2*16 + bRow)*LDSH + kk*16 + bKoff;
                uint32_t r0, r1, r2, r3;
                ldsm4(r0, r1, r2, r3, &sm[s][0][ro]);
                wh[2*j2][0] = r0; wh[2*j2][1] = r1; wh[2*j2+1][0] = r2; wh[2*j2+1][1] = r3;
                ldsm4(r0, r1, r2, r3, &sm[s][1][ro]);
                wl[2*j2][0] = r0; wl[2*j2][1] = r1; wl[2*j2+1][0] = r2; wl[2*j2+1][1] = r3;
            }
#pragma unroll
            for (int mi = 0; mi < MI; mi++)
#pragma unroll
                for (int ni = 0; ni < NI; ni++) {
                    mma16816(c[mi][ni], ah[mi], wh[ni]);
                    mma16816(c[mi][ni], ah[mi], wl[ni]);
                    mma16816(c[mi][ni], al[mi], wh[ni]);
                }
        }
        __syncthreads();
    }

    float* Cf = p.Cf ? p.Cf + (long)z * p.scz : nullptr;
#pragma unroll
    for (int mi = 0; mi < MI; mi++) {
#pragma unroll
        for (int ni = 0; ni < NI; ni++) {
            const int col = n0 + wn0 + ni*8 + (lane & 3)*2;
            float b0 = 0.f, b1 = 0.f;
            if (p.bias) { b0 = p.bias[col]; b1 = p.bias[col+1]; }
#pragma unroll
            for (int h = 0; h < 2; h++) {
                const int r = m0 + wm0 + mi*16 + (lane >> 2) + h*8;
                float v0 = c[mi][ni][h*2] + b0, v1 = c[mi][ni][h*2+1] + b1;
                if (p.add) { const float* ap = p.add + (long)r * p.add_ld + col; v0 += ap[0]; v1 += ap[1]; }
                if (p.relu) { v0 = fmaxf(v0, 0.f); v1 = fmaxf(v1, 0.f); }
                if (Cf) *(float2*)&Cf[(long)r * p.ldc + col] = make_float2(v0, v1);
                if (p.Chi) {
                    __nv_bfloat16 h0 = __float2bfloat16(v0), h1 = __float2bfloat16(v1);
                    __nv_bfloat162 hh; hh.x = h0; hh.y = h1;
                    *(__nv_bfloat162*)&p.Chi[(long)r * p.ldc + col] = hh;
                    __nv_bfloat162 ll;
                    ll.x = __float2bfloat16(v0 - __bfloat162float(h0));
                    ll.y = __float2bfloat16(v1 - __bfloat162float(h1));
                    *(__nv_bfloat162*)&p.Clo[(long)r * p.ldc + col] = ll;
                }
            }
        }
    }
}

// ===================== small kernels =====================
__global__ void k_split4(__nv_bfloat16* __restrict__ hh, __nv_bfloat16* __restrict__ ll,
                         const float* __restrict__ s, long n4)
{
    long i = (long)blockIdx.x * 256 + threadIdx.x;
    if (i >= n4) return;
    float4 v = reinterpret_cast<const float4*>(s)[i];
    float vv[4] = {v.x, v.y, v.z, v.w};
    __nv_bfloat16 h[4], l[4];
#pragma unroll
    for (int q = 0; q < 4; q++) {
        h[q] = __float2bfloat16(vv[q]);
        l[q] = __float2bfloat16(vv[q] - __bfloat162float(h[q]));
    }
    reinterpret_cast<uint2*>(hh)[i] = *(uint2*)h;
    reinterpret_cast<uint2*>(ll)[i] = *(uint2*)l;
}

__global__ void k_inith(const float* hidden)
{
    long idx = (long)blockIdx.x * 256 + threadIdx.x;
    float v = hidden[idx];
    g_hf[idx] = v;
    int l = (int)(idx >> 18); long rem = idx & 262143;
    int b = (int)(rem >> 10), j = (int)(rem & 1023);
    __nv_bfloat16 h = __float2bfloat16(v);
    __nv_bfloat16 lo = __float2bfloat16(v - __bfloat162float(h));
    __nv_bfloat16* dh = l ? g_a1h : g_a0h;
    __nv_bfloat16* dl = l ? g_a1l : g_a0l;
    dh[b*2048 + 1024 + j] = h; dl[b*2048 + 1024 + j] = lo;
}

// fused softmax + wenc: one block per batch row
__global__ void k_attn(const float* __restrict__ enc, float* __restrict__ out_attn, int t)
{
    const int b = blockIdx.x, tid = threadIdx.x;
    __shared__ float aw[NS];
    if (tid < 32) {
        const int lane = tid;
        float v[3];
#pragma unroll
        for (int u = 0; u < 3; u++) {
            const int s = u*32 + lane;
            float x = g_lx[((long)b*NT + t)*NS + s];
#pragma unroll
            for (int p = 0; p < 4; p++) x += g_lpart[p*24576 + b*NS + s];
            v[u] = x;
        }
        float mx = fmaxf(v[0], fmaxf(v[1], v[2]));
#pragma unroll
        for (int o = 16; o > 0; o >>= 1) mx = fmaxf(mx, __shfl_xor_sync(0xffffffffu, mx, o));
        float e[3], sum = 0.f;
#pragma unroll
        for (int u = 0; u < 3; u++) { e[u] = expf(v[u] - mx); sum += e[u]; }
#pragma unroll
        for (int o = 16; o > 0; o >>= 1) sum += __shfl_xor_sync(0xffffffffu, sum, o);
        const float inv = 1.0f / sum;
#pragma unroll
        for (int u = 0; u < 3; u++) {
            const int s = u*32 + lane;
            const float w = e[u] * inv;
            aw[s] = w;
            out_attn[((long)b*NT + t)*NS + s] = w;
        }
    }
    __syncthreads();
    float4 acc = make_float4(0.f, 0.f, 0.f, 0.f);
    const float4* row = reinterpret_cast<const float4*>(enc + (long)b*NS*NH) + tid;
#pragma unroll 4
    for (int s = 0; s < NS; s++) {
        const float4 q = row[(long)s * (NH/4)];
        const float w = aw[s];
        acc.x += w*q.x; acc.y += w*q.y; acc.z += w*q.z; acc.w += w*q.w;
    }
    const int base = b*1024 + tid*4;
    float vv[4] = {acc.x, acc.y, acc.z, acc.w};
    __nv_bfloat16 h[4], l[4];
#pragma unroll
    for (int i = 0; i < 4; i++) {
        h[i] = __float2bfloat16(vv[i]);
        l[i] = __float2bfloat16(vv[i] - __bfloat162float(h[i]));
    }
    *(uint2*)&g_weh[base] = *(uint2*)h;
    *(uint2*)&g_wel[base] = *(uint2*)l;
}

__global__ void k_gate(const float* __restrict__ bi, const float* __restrict__ bh,
                       float* __restrict__ hf,
                       __nv_bfloat16* d1h, __nv_bfloat16* d1l,
                       __nv_bfloat16* d2h, __nv_bfloat16* d2l,
                       __nv_bfloat16* d3h, __nv_bfloat16* d3l, long d3off)
{
    const int idx = blockIdx.x * 256 + threadIdx.x;
    const int b = idx >> 10, j = idx & 1023;
    const float* gi = g_g + (long)b * N3;
    const float* gh = g_g + 786432 + (long)b * N3;
    const float ir = gi[j] + bi[j],           hr = gh[j] + bh[j];
    const float iz = gi[j+1024] + bi[j+1024], hz = gh[j+1024] + bh[j+1024];
    const float in_ = gi[j+2048] + bi[j+2048], hn = gh[j+2048] + bh[j+2048];
    const float r = 1.0f / (1.0f + expf(-(ir + hr)));
    const float z = 1.0f / (1.0f + expf(-(iz + hz)));
    const float n = tanhf(in_ + r * hn);
    const float h = (1.0f - z) * n + z * hf[idx];
    hf[idx] = h;
    __nv_bfloat16 hh = __float2bfloat16(h);
    __nv_bfloat16 hl = __float2bfloat16(h - __bfloat162float(hh));
    const long o = (long)b*2048 + j;
    d1h[o] = hh; d1l[o] = hl;
    if (d2h) { d2h[o] = hh; d2l[o] = hl; }
    if (d3h) { const long o3 = (long)b*36864 + d3off + j; d3h[o3] = hh; d3l[o3] = hl; }
}

__global__ void k_copy(float* __restrict__ dst, const float* __restrict__ src)
{
    const long i = (long)blockIdx.x * 256 + threadIdx.x;
    dst[i] = src[i];
}

// ===================== launch =====================
extern "C" void kernel_launch(void* const* d_in, const int* in_sizes, int n_in,
                              void* d_out, int out_size)
{
    const float* target = (const float*)d_in[0];
    const float* hidden = (const float*)d_in[1];
    const float* enc    = (const float*)d_in[2];
    const float* aW     = (const float*)d_in[3];
    const float* ab     = (const float*)d_in[4];
    const float* cW     = (const float*)d_in[5];
    const float* cb     = (const float*)d_in[6];
    const float* Wih    = (const float*)d_in[7];
    const float* Whh    = (const float*)d_in[8];
    const float* bih    = (const float*)d_in[9];
    const float* bhh    = (const float*)d_in[10];
    const float* o1W    = (const float*)d_in[11];
    const float* o1b    = (const float*)d_in[12];
    const float* o2W    = (const float*)d_in[13];
    const float* o2b    = (const float*)d_in[14];

    float* out_y    = (float*)d_out;
    float* out_h    = out_y + (long)NB*NT*ND;
    float* out_attn = out_h + (long)2*NB*NH;

    __nv_bfloat16 *th, *tl, *aWh, *aWl, *cWh, *cWl, *Wgh, *Wgl, *o1h, *o1l, *o2h, *o2l;
    __nv_bfloat16 *tmph, *tmpl, *h1h, *h1l, *weh, *wel, *a0h, *a0l, *a1h, *a1l;
    float *combx, *lx, *lpart, *gg, *hf;
    cudaGetSymbolAddress((void**)&th, g_th);     cudaGetSymbolAddress((void**)&tl, g_tl);
    cudaGetSymbolAddress((void**)&aWh, g_aWh);   cudaGetSymbolAddress((void**)&aWl, g_aWl);
    cudaGetSymbolAddress((void**)&cWh, g_cWh);   cudaGetSymbolAddress((void**)&cWl, g_cWl);
    cudaGetSymbolAddress((void**)&Wgh, g_Wgh);   cudaGetSymbolAddress((void**)&Wgl, g_Wgl);
    cudaGetSymbolAddress((void**)&o1h, g_o1h);   cudaGetSymbolAddress((void**)&o1l, g_o1l);
    cudaGetSymbolAddress((void**)&o2h, g_o2h);   cudaGetSymbolAddress((void**)&o2l, g_o2l);
    cudaGetSymbolAddress((void**)&tmph, g_tmph); cudaGetSymbolAddress((void**)&tmpl, g_tmpl);
    cudaGetSymbolAddress((void**)&h1h, g_h1h);   cudaGetSymbolAddress((void**)&h1l, g_h1l);
    cudaGetSymbolAddress((void**)&weh, g_weh);   cudaGetSymbolAddress((void**)&wel, g_wel);
    cudaGetSymbolAddress((void**)&a0h, g_a0h);   cudaGetSymbolAddress((void**)&a0l, g_a0l);
    cudaGetSymbolAddress((void**)&a1h, g_a1h);   cudaGetSymbolAddress((void**)&a1l, g_a1l);
    cudaGetSymbolAddress((void**)&combx, g_combx);
    cudaGetSymbolAddress((void**)&lx, g_lx);
    cudaGetSymbolAddress((void**)&lpart, g_lpart);
    cudaGetSymbolAddress((void**)&gg, g_g);
    cudaGetSymbolAddress((void**)&hf, g_hf);

    auto g4 = [](long n) { return (unsigned)((n/4 + 255) / 256); };
    k_split4<<<g4(9216L*1024), 256>>>(th, tl, target, 9216L*1024/4);
    k_split4<<<g4(96L*2048), 256>>>(aWh, aWl, aW, 96L*2048/4);
    k_split4<<<g4(1024L*2048), 256>>>(cWh, cWl, cW, 1024L*2048/4);
    for (int l = 0; l < 2; l++) {
        k_split4<<<g4(3145728), 256>>>(Wgh + (long)(l*2+0)*3145728, Wgl + (long)(l*2+0)*3145728,
                                       Wih + (long)l*3145728, 3145728/4);
        k_split4<<<g4(3145728), 256>>>(Wgh + (long)(l*2+1)*3145728, Wgl + (long)(l*2+1)*3145728,
                                       Whh + (long)l*3145728, 3145728/4);
    }
    k_split4<<<g4(1048576), 256>>>(o1h, o1l, o1W, 1048576/4);
    k_split4<<<g4(1048576), 256>>>(o2h, o2l, o2W, 1048576/4);
    k_inith<<<2048, 256>>>(hidden);

    GP p = {};

    // ---- pre: x-parts ----
    p = {}; p.Ah = th; p.Al = tl; p.lda = 1024; p.Wh = aWh; p.Wl = aWl; p.ldw = 2048;
    p.Cf = lx; p.ldc = 96; p.bias = ab; p.K = 1024;
    gemm_bf16<64,32,32,16><<<dim3(3,144,1), 128>>>(p);
    p = {}; p.Ah = th; p.Al = tl; p.lda = 1024; p.Wh = cWh; p.Wl = cWl; p.ldw = 2048;
    p.Cf = combx; p.ldc = 1024; p.bias = cb; p.K = 1024;
    gemm_bf16<64,64,32,32><<<dim3(16,144,1), 128>>>(p);

    // ---- recurrent loop ----
    for (int t = 0; t < NT; t++) {
        p = {}; p.Ah = a1h + 1024; p.Al = a1l + 1024; p.lda = 2048;
        p.Wh = aWh + 1024; p.Wl = aWl + 1024; p.ldw = 2048;
        p.Cf = lpart; p.scz = 24576; p.ldc = 96; p.K = 256; p.kz = 256;
        gemm_bf16<64,32,32,16><<<dim3(3,4,4), 128>>>(p);

        k_attn<<<256, 256>>>(enc, out_attn, t);

        p = {}; p.Ah = weh; p.Al = wel; p.lda = 1024;
        p.Wh = cWh + 1024; p.Wl = cWl + 1024; p.ldw = 2048;
        p.Chi = a0h; p.Clo = a0l; p.ldc = 2048;
        p.add = combx + (long)t*1024; p.add_ld = 36864; p.relu = 1; p.K = 1024;
        gemm_bf16<64,64,32,32><<<dim3(16,4,1), 128>>>(p);

        p = {}; p.Ah = a0h; p.Al = a0l; p.lda = 2048; p.saz = 1024;
        p.Wh = Wgh; p.Wl = Wgl; p.ldw = 1024; p.swz = 3145728;
        p.Cf = gg; p.scz = 786432; p.ldc = 3072; p.K = 1024;
        gemm_bf16<64,64,32,32><<<dim3(48,4,2), 128>>>(p);
        k_gate<<<1024, 256>>>(bih, bhh, hf, a1h, a1l, a0h + 1024, a0l + 1024,
                              nullptr, nullptr, 0);

        p = {}; p.Ah = a1h; p.Al = a1l; p.lda = 2048; p.saz = 1024;
        p.Wh = Wgh + 2L*3145728; p.Wl = Wgl + 2L*3145728; p.ldw = 1024; p.swz = 3145728;
        p.Cf = gg; p.scz = 786432; p.ldc = 3072; p.K = 1024;
        gemm_bf16<64,64,32,32><<<dim3(48,4,2), 128>>>(p);
        k_gate<<<1024, 256>>>(bih + 3072, bhh + 3072, hf + 262144, a1h + 1024, a1l + 1024,
                              nullptr, nullptr, h1h, h1l, (long)t*1024);
    }

    // ---- deferred output head ----
    p = {}; p.Ah = h1h; p.Al = h1l; p.lda = 1024; p.Wh = o1h; p.Wl = o1l; p.ldw = 1024;
    p.Chi = tmph; p.Clo = tmpl; p.ldc = 1024; p.bias = o1b; p.K = 1024;
    gemm_bf16<64,64,32,32><<<dim3(16,144,1), 128>>>(p);
    p = {}; p.Ah = tmph; p.Al = tmpl; p.lda = 1024; p.Wh = o2h; p.Wl = o2l; p.ldw = 1024;
    p.Cf = out_y; p.ldc = 1024; p.bias = o2b; p.K = 1024;
    gemm_bf16<64,64,32,32><<<dim3(16,144,1), 128>>>(p);

    k_copy<<<2048, 256>>>(out_h, hf);
}